// round 14
// baseline (speedup 1.0000x reference)
#include <cuda_runtime.h>
#include <cstdint>

#define D_MODEL 1024
#define NH      16
#define HDIM    64
#define B_      8
#define TQ      1024
#define NKV     1536
#define SCALE   0.125f   // HD^-0.5 (exact power of two)

// attention tiles
#define BQ     128
#define BKV    64
#define LDS_P  68
#define LDS_K  68
#define LDS_V  72
#define STAGES 2
// gemm ring
#define GSTAGES 3

// Scratch (allocation-free rule: __device__ globals)
__device__ float g_q[B_ * TQ * D_MODEL];      // tf32(q_proj*SCALE)
__device__ float g_k[B_ * NKV * D_MODEL];     // tf32(k_proj)
__device__ float g_v[B_ * NKV * D_MODEL];     // tf32(v_proj)
__device__ float g_ctx[B_ * TQ * D_MODEL];    // tf32(attn out), K-permuted
__device__ float g_qin[B_ * TQ * D_MODEL];    // tf32(query), K-permuted
__device__ float g_kvin[B_ * NKV * D_MODEL];  // tf32(key_value), K-permuted
__device__ float g_wq[D_MODEL * D_MODEL];     // tf32 weights, K-permuted
__device__ float g_wk[D_MODEL * D_MODEL];
__device__ float g_wv[D_MODEL * D_MODEL];
__device__ float g_wo[D_MODEL * D_MODEL];

// ---------------------------------------------------------------------------
__device__ __forceinline__ float to_tf32(float x) {
    uint32_t y;
    asm("cvt.rna.tf32.f32 %0, %1;" : "=r"(y) : "f"(x));
    return __uint_as_float(y);
}

__device__ __forceinline__ void mma_tf32_16x8x8(
    float& c0, float& c1, float& c2, float& c3,
    uint32_t a0, uint32_t a1, uint32_t a2, uint32_t a3,
    uint32_t b0, uint32_t b1)
{
    asm volatile(
        "mma.sync.aligned.m16n8k8.row.col.f32.tf32.tf32.f32 "
        "{%0,%1,%2,%3}, {%4,%5,%6,%7}, {%8,%9}, {%0,%1,%2,%3};\n"
        : "+f"(c0), "+f"(c1), "+f"(c2), "+f"(c3)
        : "r"(a0), "r"(a1), "r"(a2), "r"(a3), "r"(b0), "r"(b1));
}

__device__ __forceinline__ uint32_t smem_u32(const void* p) {
    uint32_t a;
    asm("{ .reg .u64 t; cvta.to.shared.u64 t, %1; cvt.u32.u64 %0, t; }"
        : "=r"(a) : "l"(p));
    return a;
}

#define CP_ASYNC16(dst, src) \
    asm volatile("cp.async.cg.shared.global [%0], [%1], 16;" \
                 :: "r"(dst), "l"(src) : "memory")
#define CP_COMMIT() asm volatile("cp.async.commit_group;" ::: "memory")
#define CP_WAIT(n)  asm volatile("cp.async.wait_group %0;" :: "n"(n) : "memory")

// K-permutation within each 8-group: logical j -> physical (j<4 ? 2j : 2(j-4)+1)
// so fragment slots (tig, tig+4) sit at adjacent physical cols (2tig, 2tig+1).

// ---------------------------------------------------------------------------
// Fused tf32 rounding + K-permutation over all 6 GEMM input arrays.
// Each thread handles 8 consecutive floats (one permutation group).
// ---------------------------------------------------------------------------
__global__ __launch_bounds__(256) void cvt_all_kernel(
    const float* __restrict__ query, float* __restrict__ qin,
    const float* __restrict__ kv,    float* __restrict__ kvin,
    const float* __restrict__ Wq, float* __restrict__ wq,
    const float* __restrict__ Wk, float* __restrict__ wk,
    const float* __restrict__ Wv, float* __restrict__ wv,
    const float* __restrict__ Wo, float* __restrict__ wo)
{
    const int NQ = B_ * TQ * D_MODEL;
    const int NKVE = B_ * NKV * D_MODEL;
    const int NW = D_MODEL * D_MODEL;
    int i = (blockIdx.x * 256 + threadIdx.x) * 8;
    const float* src; float* dst; int off;
    if (i < NQ)                       { src = query; dst = qin;  off = i; }
    else if (i < NQ + NKVE)           { src = kv;    dst = kvin; off = i - NQ; }
    else if (i < NQ + NKVE + NW)      { src = Wq; dst = wq; off = i - NQ - NKVE; }
    else if (i < NQ + NKVE + 2 * NW)  { src = Wk; dst = wk; off = i - NQ - NKVE - NW; }
    else if (i < NQ + NKVE + 3 * NW)  { src = Wv; dst = wv; off = i - NQ - NKVE - 2 * NW; }
    else                              { src = Wo; dst = wo; off = i - NQ - NKVE - 3 * NW; }
    float4 lo = *(const float4*)(src + off);
    float4 hi = *(const float4*)(src + off + 4);
    float s0 = to_tf32(lo.x), s1 = to_tf32(lo.y), s2 = to_tf32(lo.z), s3 = to_tf32(lo.w);
    float s4 = to_tf32(hi.x), s5 = to_tf32(hi.y), s6 = to_tf32(hi.z), s7 = to_tf32(hi.w);
    // physical[p] = logical j with perm(j)=p: (s0,s4,s1,s5),(s2,s6,s3,s7)
    *(float4*)(dst + off)     = make_float4(s0, s4, s1, s5);
    *(float4*)(dst + off + 4) = make_float4(s2, s6, s3, s7);
}

// ---------------------------------------------------------------------------
// GEMM body: C tile = A @ W^T + bias (N=K=1024). A and W K-PERMUTED in gmem;
// fragment loads are LDS.64 (adjacent slot pairs). cp.async 3-stage ring.
// Numerics bit-identical to R13 (same logical operand in same mma slot).
// ---------------------------------------------------------------------------
__device__ __forceinline__ void gemm_body(
    float* gsm,
    const float* __restrict__ A, const float* __restrict__ W,
    const float* __restrict__ bias, float* __restrict__ C,
    int bm, int bn, float oscale, int oround)
{
    const int N = D_MODEL, K = D_MODEL;
    float* As = gsm;                          // [3][128][36]
    float* Bs = gsm + GSTAGES * 128 * 36;     // [3][128][36]
    const uint32_t as_u32 = smem_u32(As);
    const uint32_t bs_u32 = smem_u32(Bs);

    const int tid  = threadIdx.x;
    const int wid  = tid >> 5;
    const int lane = tid & 31;
    const int g    = lane >> 2;
    const int tig  = lane & 3;
    const int warp_m = (wid >> 2) * 64;
    const int warp_n = (wid & 3) * 32;

    const int crow = tid >> 3;
    const int ccol = (tid & 7) * 4;

    const float* aptr = A + (size_t)(bm + crow) * K + ccol;
    const float* bptr = W + (size_t)(bn + crow) * K + ccol;

    float acc[4][4][4];
#pragma unroll
    for (int mf = 0; mf < 4; mf++)
#pragma unroll
        for (int nf = 0; nf < 4; nf++)
#pragma unroll
            for (int r = 0; r < 4; r++) acc[mf][nf][r] = 0.f;

#pragma unroll
    for (int p = 0; p < 2; p++) {
        const float* ap = aptr + (size_t)p * 32;
        const float* bp = bptr + (size_t)p * 32;
        const int so = p * 128 * 36;
#pragma unroll
        for (int u = 0; u < 4; u++) {
            int r = crow + u * 32;
            CP_ASYNC16(as_u32 + (uint32_t)(so + r * 36 + ccol) * 4,
                       ap + (size_t)u * 32 * K);
            CP_ASYNC16(bs_u32 + (uint32_t)(so + r * 36 + ccol) * 4,
                       bp + (size_t)u * 32 * K);
        }
        CP_COMMIT();
    }

    const int kTiles = K >> 5;
    int cur = 0, nslot = 2;
    for (int kt = 0; kt < kTiles; kt++) {
        CP_WAIT(1);
        __syncthreads();
        if (kt + 2 < kTiles) {
            const float* ap = aptr + (size_t)(kt + 2) * 32;
            const float* bp = bptr + (size_t)(kt + 2) * 32;
            const int so = nslot * 128 * 36;
#pragma unroll
            for (int u = 0; u < 4; u++) {
                int r = crow + u * 32;
                CP_ASYNC16(as_u32 + (uint32_t)(so + r * 36 + ccol) * 4,
                           ap + (size_t)u * 32 * K);
                CP_ASYNC16(bs_u32 + (uint32_t)(so + r * 36 + ccol) * 4,
                           bp + (size_t)u * 32 * K);
            }
        }
        CP_COMMIT();

        const int co = cur * 128 * 36;
#pragma unroll
        for (int ks = 0; ks < 4; ks++) {
            const int k0 = ks * 8 + 2 * tig;   // physical base of (tig, tig+4) pair
            uint32_t af[4][4];
#pragma unroll
            for (int mf = 0; mf < 4; mf++) {
                int row = warp_m + mf * 16;
                float2 p0 = *(const float2*)&As[co + (row + g    ) * 36 + k0];
                float2 p1 = *(const float2*)&As[co + (row + g + 8) * 36 + k0];
                af[mf][0] = __float_as_uint(p0.x);   // logical tig
                af[mf][2] = __float_as_uint(p0.y);   // logical tig+4
                af[mf][1] = __float_as_uint(p1.x);
                af[mf][3] = __float_as_uint(p1.y);
            }
            uint32_t bf[4][2];
#pragma unroll
            for (int nf = 0; nf < 4; nf++) {
                int col = warp_n + nf * 8;
                float2 pb = *(const float2*)&Bs[co + (col + g) * 36 + k0];
                bf[nf][0] = __float_as_uint(pb.x);
                bf[nf][1] = __float_as_uint(pb.y);
            }
#pragma unroll
            for (int mf = 0; mf < 4; mf++)
#pragma unroll
                for (int nf = 0; nf < 4; nf++)
                    mma_tf32_16x8x8(acc[mf][nf][0], acc[mf][nf][1],
                                    acc[mf][nf][2], acc[mf][nf][3],
                                    af[mf][0], af[mf][1], af[mf][2], af[mf][3],
                                    bf[nf][0], bf[nf][1]);
        }
        cur   = (cur + 1 == GSTAGES) ? 0 : cur + 1;
        nslot = (nslot + 1 == GSTAGES) ? 0 : nslot + 1;
    }

#pragma unroll
    for (int mf = 0; mf < 4; mf++) {
        int row0 = bm + warp_m + mf * 16 + g;
#pragma unroll
        for (int nf = 0; nf < 4; nf++) {
            int col = bn + warp_n + nf * 8 + 2 * tig;
            float bv0 = bias[col], bv1 = bias[col + 1];
            float v00 = (acc[mf][nf][0] + bv0) * oscale;
            float v01 = (acc[mf][nf][1] + bv1) * oscale;
            float v10 = (acc[mf][nf][2] + bv0) * oscale;
            float v11 = (acc[mf][nf][3] + bv1) * oscale;
            if (oround) {
                v00 = to_tf32(v00); v01 = to_tf32(v01);
                v10 = to_tf32(v10); v11 = to_tf32(v11);
            }
            *(float2*)&C[(size_t)row0 * N + col]       = make_float2(v00, v01);
            *(float2*)&C[(size_t)(row0 + 8) * N + col] = make_float2(v10, v11);
        }
    }
}

// ---------------------------------------------------------------------------
__global__ __launch_bounds__(256, 2) void gemm_qkv_fused(
    const float* __restrict__ qin, const float* __restrict__ kvin,
    const float* __restrict__ wq, const float* __restrict__ bq, float* __restrict__ qb,
    const float* __restrict__ wk, const float* __restrict__ bk, float* __restrict__ kb,
    const float* __restrict__ wv, const float* __restrict__ bv, float* __restrict__ vb)
{
    extern __shared__ float gsm[];
    const int y = blockIdx.y;
    const int bn = blockIdx.x * 128;
    if (y < 64) {
        gemm_body(gsm, qin, wq, bq, qb, y * 128, bn, SCALE, 1);
    } else if (y < 160) {
        gemm_body(gsm, kvin, wk, bk, kb, (y - 64) * 128, bn, 1.0f, 1);
    } else {
        gemm_body(gsm, kvin, wv, bv, vb, (y - 160) * 128, bn, 1.0f, 1);
    }
}

__global__ __launch_bounds__(256, 2) void gemm_o_proj(
    const float* __restrict__ cb, const float* __restrict__ wo,
    const float* __restrict__ bo, float* __restrict__ out)
{
    extern __shared__ float gsm[];
    gemm_body(gsm, cb, wo, bo, out, blockIdx.y * 128, blockIdx.x * 128, 1.0f, 0);
}

// ---------------------------------------------------------------------------
__device__ __forceinline__ void stage_kv(
    uint32_t ks_u32, uint32_t vs_u32, uint32_t ms_u32, int slot,
    const float* kp, const float* vp, const unsigned char* mp,
    int sr, int sc, int tid)
{
#pragma unroll
    for (int u = 0; u < 4; u++) {
        int r = sr + u * 16;
        CP_ASYNC16(ks_u32 + (uint32_t)(slot * BKV * LDS_K + r * LDS_K + sc) * 4,
                   kp + (size_t)r * D_MODEL + sc);
        CP_ASYNC16(vs_u32 + (uint32_t)(slot * BKV * LDS_V + r * LDS_V + sc) * 4,
                   vp + (size_t)r * D_MODEL + sc);
    }
    if (tid < 4)
        CP_ASYNC16(ms_u32 + (uint32_t)(slot * BKV + tid * 16), mp + tid * 16);
}

// ---------------------------------------------------------------------------
// Tensor-core flash attention (unchanged compute). Epilogue writes ctx with
// the K-permutation (o_proj input), tf32-rounded. Same float values, moved.
// ---------------------------------------------------------------------------
__global__ __launch_bounds__(256, 2) void attn_tc_kernel(
    const float* __restrict__ qb, const float* __restrict__ kb,
    const float* __restrict__ vb, const unsigned char* __restrict__ mask,
    float* __restrict__ ctx)
{
    extern __shared__ float sm[];
    float* Ps = sm;
    float* Ks = Ps + BQ * LDS_P;
    float* Vs = Ks + STAGES * BKV * LDS_K;
    unsigned char* Ms = (unsigned char*)(Vs + STAGES * BKV * LDS_V);

    const int tid  = threadIdx.x;
    const int wid  = tid >> 5;
    const int lane = tid & 31;
    const int g    = lane >> 2;
    const int tig  = lane & 3;
    const int qr0  = wid * 16;
    const int b = blockIdx.y / NH;
    const int h = blockIdx.y % NH;
    const int t0 = blockIdx.x * BQ;

    const int sr = tid >> 4;
    const int sc = (tid & 15) * 4;

    const uint32_t ps_u32 = smem_u32(Ps);
    const uint32_t ks_u32 = smem_u32(Ks);
    const uint32_t vs_u32 = smem_u32(Vs);
    const uint32_t ms_u32 = smem_u32(Ms);

    const float* qbase = qb + ((size_t)b * TQ + t0) * D_MODEL + h * HDIM;
    const float* kbase = kb + ((size_t)b * NKV) * D_MODEL + h * HDIM;
    const float* vbase = vb + ((size_t)b * NKV) * D_MODEL + h * HDIM;
    const unsigned char* mbase = mask + (size_t)b * NKV;

#pragma unroll
    for (int u = 0; u < 8; u++) {
        int idx = tid + u * 256;
        int r = idx >> 4, c = (idx & 15) * 4;
        CP_ASYNC16(ps_u32 + (uint32_t)(r * LDS_P + c) * 4,
                   qbase + (size_t)r * D_MODEL + c);
    }
    CP_COMMIT();
    stage_kv(ks_u32, vs_u32, ms_u32, 0, kbase, vbase, mbase, sr, sc, tid);
    CP_COMMIT();

    CP_WAIT(1);
    __syncthreads();

    uint32_t qa[8][4];
#pragma unroll
    for (int ks = 0; ks < 8; ks++) {
        int k0 = ks * 8;
        qa[ks][0] = __float_as_uint(Ps[(qr0 + g    ) * LDS_P + k0 + tig    ]);
        qa[ks][1] = __float_as_uint(Ps[(qr0 + g + 8) * LDS_P + k0 + tig    ]);
        qa[ks][2] = __float_as_uint(Ps[(qr0 + g    ) * LDS_P + k0 + tig + 4]);
        qa[ks][3] = __float_as_uint(Ps[(qr0 + g + 8) * LDS_P + k0 + tig + 4]);
    }

    float m0 = -1e30f, m1 = -1e30f, l0 = 0.f, l1 = 0.f;
    float o[8][4];
#pragma unroll
    for (int df = 0; df < 8; df++)
#pragma unroll
        for (int r = 0; r < 4; r++) o[df][r] = 0.f;

    const int nTiles = NKV / BKV;
    for (int t = 0; t < nTiles; t++) {
        const int slot = t & 1;
        CP_WAIT(0);
        __syncthreads();

        if (t + 1 < nTiles) {
            stage_kv(ks_u32, vs_u32, ms_u32, 1 - slot,
                     kbase + (size_t)(t + 1) * BKV * D_MODEL,
                     vbase + (size_t)(t + 1) * BKV * D_MODEL,
                     mbase + (t + 1) * BKV, sr, sc, tid);
        }
        CP_COMMIT();

        const int cK = slot * BKV * LDS_K;
        const int cV = slot * BKV * LDS_V;
        const int cM = slot * BKV;

        float s[8][4];
#pragma unroll
        for (int nf = 0; nf < 8; nf++) {
            s[nf][0] = 0.f; s[nf][1] = 0.f; s[nf][2] = 0.f; s[nf][3] = 0.f;
#pragma unroll
            for (int ks = 0; ks < 8; ks++) {
                int k0 = ks * 8;
                uint32_t b0 = __float_as_uint(Ks[cK + (nf * 8 + g) * LDS_K + k0 + tig    ]);
                uint32_t b1 = __float_as_uint(Ks[cK + (nf * 8 + g) * LDS_K + k0 + tig + 4]);
                mma_tf32_16x8x8(s[nf][0], s[nf][1], s[nf][2], s[nf][3],
                                qa[ks][0], qa[ks][1], qa[ks][2], qa[ks][3], b0, b1);
            }
        }

#pragma unroll
        for (int nf = 0; nf < 8; nf++) {
            int c0 = cM + nf * 8 + 2 * tig;
            if (Ms[c0])     { s[nf][0] = -1e30f; s[nf][2] = -1e30f; }
            if (Ms[c0 + 1]) { s[nf][1] = -1e30f; s[nf][3] = -1e30f; }
        }

        float rmax0 = -1e30f, rmax1 = -1e30f;
#pragma unroll
        for (int nf = 0; nf < 8; nf++) {
            rmax0 = fmaxf(rmax0, fmaxf(s[nf][0], s[nf][1]));
            rmax1 = fmaxf(rmax1, fmaxf(s[nf][2], s[nf][3]));
        }
        rmax0 = fmaxf(rmax0, __shfl_xor_sync(0xffffffffu, rmax0, 1));
        rmax0 = fmaxf(rmax0, __shfl_xor_sync(0xffffffffu, rmax0, 2));
        rmax1 = fmaxf(rmax1, __shfl_xor_sync(0xffffffffu, rmax1, 1));
        rmax1 = fmaxf(rmax1, __shfl_xor_sync(0xffffffffu, rmax1, 2));

        float mn0 = fmaxf(m0, rmax0), mn1 = fmaxf(m1, rmax1);
        float corr0 = __expf(m0 - mn0), corr1 = __expf(m1 - mn1);
        m0 = mn0; m1 = mn1;

        float rs0 = 0.f, rs1 = 0.f;
#pragma unroll
        for (int nf = 0; nf < 8; nf++) {
            s[nf][0] = __expf(s[nf][0] - mn0); rs0 += s[nf][0];
            s[nf][1] = __expf(s[nf][1] - mn0); rs0 += s[nf][1];
            s[nf][2] = __expf(s[nf][2] - mn1); rs1 += s[nf][2];
            s[nf][3] = __expf(s[nf][3] - mn1); rs1 += s[nf][3];
        }
        rs0 += __shfl_xor_sync(0xffffffffu, rs0, 1);
        rs0 += __shfl_xor_sync(0xffffffffu, rs0, 2);
        rs1 += __shfl_xor_sync(0xffffffffu, rs1, 1);
        rs1 += __shfl_xor_sync(0xffffffffu, rs1, 2);
        l0 = l0 * corr0 + rs0;
        l1 = l1 * corr1 + rs1;

#pragma unroll
        for (int nf = 0; nf < 8; nf++) {
            int col = nf * 8 + 2 * tig;
            *(float2*)&Ps[(qr0 + g    ) * LDS_P + col] =
                make_float2(to_tf32(s[nf][0]), to_tf32(s[nf][1]));
            *(float2*)&Ps[(qr0 + g + 8) * LDS_P + col] =
                make_float2(to_tf32(s[nf][2]), to_tf32(s[nf][3]));
        }
        __syncwarp();

#pragma unroll
        for (int df = 0; df < 8; df++) {
            o[df][0] *= corr0; o[df][1] *= corr0;
            o[df][2] *= corr1; o[df][3] *= corr1;
        }
#pragma unroll
        for (int ks = 0; ks < 8; ks++) {
            int k0 = ks * 8;
            uint32_t pa0 = __float_as_uint(Ps[(qr0 + g    ) * LDS_P + k0 + tig    ]);
            uint32_t pa1 = __float_as_uint(Ps[(qr0 + g + 8) * LDS_P + k0 + tig    ]);
            uint32_t pa2 = __float_as_uint(Ps[(qr0 + g    ) * LDS_P + k0 + tig + 4]);
            uint32_t pa3 = __float_as_uint(Ps[(qr0 + g + 8) * LDS_P + k0 + tig + 4]);
#pragma unroll
            for (int df = 0; df < 8; df++) {
                uint32_t vb0 = __float_as_uint(Vs[cV + (k0 + tig    ) * LDS_V + df * 8 + g]);
                uint32_t vb1 = __float_as_uint(Vs[cV + (k0 + tig + 4) * LDS_V + df * 8 + g]);
                mma_tf32_16x8x8(o[df][0], o[df][1], o[df][2], o[df][3],
                                pa0, pa1, pa2, pa3, vb0, vb1);
            }
        }
    }

    // ---- normalize, tf32-round, write ctx with K-permutation ----
    // logical cols (2tig, 2tig+1) in group df*8 -> physical perm(2tig), perm(2tig+1)
    // perm: 0->0,1->2,2->4,3->6,4->1,5->3,6->5,7->7
    float inv0 = 1.f / l0, inv1 = 1.f / l1;
    float* obase = ctx + ((size_t)b * TQ + t0) * D_MODEL + h * HDIM;
    const int j0 = 2 * tig;                     // logical even col
    const int p0 = (j0 < 4) ? 2 * j0 : 2 * (j0 - 4) + 1;
    const int p1 = ((j0 + 1) < 4) ? 2 * (j0 + 1) : 2 * (j0 + 1 - 4) + 1;
#pragma unroll
    for (int df = 0; df < 8; df++) {
        int base = df * 8;
        float* r0 = &obase[(size_t)(qr0 + g    ) * D_MODEL + base];
        float* r1 = &obase[(size_t)(qr0 + g + 8) * D_MODEL + base];
        r0[p0] = to_tf32(o[df][0] * inv0);
        r0[p1] = to_tf32(o[df][1] * inv0);
        r1[p0] = to_tf32(o[df][2] * inv1);
        r1[p1] = to_tf32(o[df][3] * inv1);
    }
}

// ---------------------------------------------------------------------------
extern "C" void kernel_launch(void* const* d_in, const int* in_sizes, int n_in,
                              void* d_out, int out_size)
{
    const float* query = (const float*)d_in[0];
    const float* kv    = (const float*)d_in[1];
    const unsigned char* mask = (const unsigned char*)d_in[2];
    const float* Wq = (const float*)d_in[3];
    const float* bq = (const float*)d_in[4];
    const float* Wk = (const float*)d_in[5];
    const float* bk = (const float*)d_in[6];
    const float* Wv = (const float*)d_in[7];
    const float* bv = (const float*)d_in[8];
    const float* Wo = (const float*)d_in[9];
    const float* bo = (const float*)d_in[10];
    float* out = (float*)d_out;

    static float *qb = nullptr, *kb = nullptr, *vbuf = nullptr, *cb = nullptr;
    static float *qin = nullptr, *kvin = nullptr;
    static float *wq = nullptr, *wk = nullptr, *wv = nullptr, *wo = nullptr;
    static const int SMEM_GEMM = GSTAGES * 2 * 128 * 36 * 4;              // 110592
    static const int SMEM_ATTN =
        (BQ * LDS_P + STAGES * BKV * LDS_K + STAGES * BKV * LDS_V) * 4
        + STAGES * BKV;                                                    // 106624
    if (!qb) {
        cudaGetSymbolAddress((void**)&qb,   g_q);
        cudaGetSymbolAddress((void**)&kb,   g_k);
        cudaGetSymbolAddress((void**)&vbuf, g_v);
        cudaGetSymbolAddress((void**)&cb,   g_ctx);
        cudaGetSymbolAddress((void**)&qin,  g_qin);
        cudaGetSymbolAddress((void**)&kvin, g_kvin);
        cudaGetSymbolAddress((void**)&wq,   g_wq);
        cudaGetSymbolAddress((void**)&wk,   g_wk);
        cudaGetSymbolAddress((void**)&wv,   g_wv);
        cudaGetSymbolAddress((void**)&wo,   g_wo);
        cudaFuncSetAttribute(gemm_qkv_fused,
                             cudaFuncAttributeMaxDynamicSharedMemorySize, SMEM_GEMM);
        cudaFuncSetAttribute(gemm_o_proj,
                             cudaFuncAttributeMaxDynamicSharedMemorySize, SMEM_GEMM);
        cudaFuncSetAttribute(attn_tc_kernel,
                             cudaFuncAttributeMaxDynamicSharedMemorySize, SMEM_ATTN);
    }

    dim3 blk(256);
    // tf32 rounding + K-permutation of all GEMM inputs (25165824 / 8 / 256)
    cvt_all_kernel<<<12288, blk>>>(query, qin, kv, kvin,
                                   Wq, wq, Wk, wk, Wv, wv, Wo, wo);

    gemm_qkv_fused<<<dim3(8, 256), blk, SMEM_GEMM>>>(
        qin, kvin, wq, bq, qb, wk, bk, kb, wv, bv, vbuf);

    attn_tc_kernel<<<dim3(TQ / BQ, B_ * NH), blk, SMEM_ATTN>>>(qb, kb, vbuf, mask, cb);

    gemm_o_proj<<<dim3(8, 64), blk, SMEM_GEMM>>>(cb, wo, bo, out);
}

// round 16
// speedup vs baseline: 1.1035x; 1.1035x over previous
#include <cuda_runtime.h>
#include <cstdint>

#define D_MODEL 1024
#define NH      16
#define HDIM    64
#define B_      8
#define TQ      1024
#define NKV     1536
#define SCALE   0.125f   // HD^-0.5 (exact power of two)

// attention tiles
#define BQ     128
#define BKV    64
#define LDS_P  68
#define LDS_K  68
#define LDS_V  72
#define STAGES 2
// gemm ring
#define GSTAGES 3

// Scratch (allocation-free rule: __device__ globals)
__device__ float g_q[B_ * TQ * D_MODEL];      // tf32(q_proj*SCALE)
__device__ float g_k[B_ * NKV * D_MODEL];     // tf32(k_proj)
__device__ float g_v[B_ * NKV * D_MODEL];     // tf32(v_proj)
__device__ float g_ctx[B_ * TQ * D_MODEL];    // tf32(attention out)
__device__ float g_qin[B_ * TQ * D_MODEL];    // tf32(query)
__device__ float g_kvin[B_ * NKV * D_MODEL];  // tf32(key_value)
__device__ float g_wq[D_MODEL * D_MODEL];     // tf32 weights
__device__ float g_wk[D_MODEL * D_MODEL];
__device__ float g_wv[D_MODEL * D_MODEL];
__device__ float g_wo[D_MODEL * D_MODEL];

// ---------------------------------------------------------------------------
__device__ __forceinline__ float to_tf32(float x) {
    uint32_t y;
    asm("cvt.rna.tf32.f32 %0, %1;" : "=r"(y) : "f"(x));
    return __uint_as_float(y);
}

__device__ __forceinline__ void mma_tf32_16x8x8(
    float& c0, float& c1, float& c2, float& c3,
    uint32_t a0, uint32_t a1, uint32_t a2, uint32_t a3,
    uint32_t b0, uint32_t b1)
{
    asm volatile(
        "mma.sync.aligned.m16n8k8.row.col.f32.tf32.tf32.f32 "
        "{%0,%1,%2,%3}, {%4,%5,%6,%7}, {%8,%9}, {%0,%1,%2,%3};\n"
        : "+f"(c0), "+f"(c1), "+f"(c2), "+f"(c3)
        : "r"(a0), "r"(a1), "r"(a2), "r"(a3), "r"(b0), "r"(b1));
}

__device__ __forceinline__ uint32_t smem_u32(const void* p) {
    uint32_t a;
    asm("{ .reg .u64 t; cvta.to.shared.u64 t, %1; cvt.u32.u64 %0, t; }"
        : "=r"(a) : "l"(p));
    return a;
}

#define CP_ASYNC16(dst, src) \
    asm volatile("cp.async.cg.shared.global [%0], [%1], 16;" \
                 :: "r"(dst), "l"(src) : "memory")
#define CP_COMMIT() asm volatile("cp.async.commit_group;" ::: "memory")
#define CP_WAIT(n)  asm volatile("cp.async.wait_group %0;" :: "n"(n) : "memory")

// ---------------------------------------------------------------------------
// Fused elementwise tf32 rounding over all 6 input arrays (one launch).
// 16 floats per thread (4 independent float4s) for MLP; no permutation.
// ---------------------------------------------------------------------------
__global__ __launch_bounds__(256) void cvt_all_kernel(
    const float* __restrict__ query, float* __restrict__ qin,
    const float* __restrict__ kv,    float* __restrict__ kvin,
    const float* __restrict__ Wq, float* __restrict__ wq,
    const float* __restrict__ Wk, float* __restrict__ wk,
    const float* __restrict__ Wv, float* __restrict__ wv,
    const float* __restrict__ Wo, float* __restrict__ wo)
{
    const int NQ = B_ * TQ * D_MODEL;          // 8388608
    const int NKVE = B_ * NKV * D_MODEL;       // 12582912
    const int NW = D_MODEL * D_MODEL;          // 1048576
    int i = (blockIdx.x * 256 + threadIdx.x) * 16;
    const float* src; float* dst; int off;
    if (i < NQ)                       { src = query; dst = qin;  off = i; }
    else if (i < NQ + NKVE)           { src = kv;    dst = kvin; off = i - NQ; }
    else if (i < NQ + NKVE + NW)      { src = Wq; dst = wq; off = i - NQ - NKVE; }
    else if (i < NQ + NKVE + 2 * NW)  { src = Wk; dst = wk; off = i - NQ - NKVE - NW; }
    else if (i < NQ + NKVE + 3 * NW)  { src = Wv; dst = wv; off = i - NQ - NKVE - 2 * NW; }
    else                              { src = Wo; dst = wo; off = i - NQ - NKVE - 3 * NW; }
    float4 v0 = *(const float4*)(src + off);
    float4 v1 = *(const float4*)(src + off + 4);
    float4 v2 = *(const float4*)(src + off + 8);
    float4 v3 = *(const float4*)(src + off + 12);
    v0.x = to_tf32(v0.x); v0.y = to_tf32(v0.y); v0.z = to_tf32(v0.z); v0.w = to_tf32(v0.w);
    v1.x = to_tf32(v1.x); v1.y = to_tf32(v1.y); v1.z = to_tf32(v1.z); v1.w = to_tf32(v1.w);
    v2.x = to_tf32(v2.x); v2.y = to_tf32(v2.y); v2.z = to_tf32(v2.z); v2.w = to_tf32(v2.w);
    v3.x = to_tf32(v3.x); v3.y = to_tf32(v3.y); v3.z = to_tf32(v3.z); v3.w = to_tf32(v3.w);
    *(float4*)(dst + off)      = v0;
    *(float4*)(dst + off + 4)  = v1;
    *(float4*)(dst + off + 8)  = v2;
    *(float4*)(dst + off + 12) = v3;
}

// ---------------------------------------------------------------------------
// GEMM body (R13): C tile = A @ W^T + bias (N=K=1024). Inputs pre-rounded
// tf32; cp.async 3-stage ring (CP_WAIT(1)). Scalar conflict-free LDS.
// ---------------------------------------------------------------------------
__device__ __forceinline__ void gemm_body(
    float* gsm,
    const float* __restrict__ A, const float* __restrict__ W,
    const float* __restrict__ bias, float* __restrict__ C,
    int bm, int bn, float oscale, int oround)
{
    const int N = D_MODEL, K = D_MODEL;
    float* As = gsm;                          // [3][128][36]
    float* Bs = gsm + GSTAGES * 128 * 36;     // [3][128][36]
    const uint32_t as_u32 = smem_u32(As);
    const uint32_t bs_u32 = smem_u32(Bs);

    const int tid  = threadIdx.x;
    const int wid  = tid >> 5;
    const int lane = tid & 31;
    const int g    = lane >> 2;
    const int tig  = lane & 3;
    const int warp_m = (wid >> 2) * 64;
    const int warp_n = (wid & 3) * 32;

    const int crow = tid >> 3;
    const int ccol = (tid & 7) * 4;

    const float* aptr = A + (size_t)(bm + crow) * K + ccol;
    const float* bptr = W + (size_t)(bn + crow) * K + ccol;

    float acc[4][4][4];
#pragma unroll
    for (int mf = 0; mf < 4; mf++)
#pragma unroll
        for (int nf = 0; nf < 4; nf++)
#pragma unroll
            for (int r = 0; r < 4; r++) acc[mf][nf][r] = 0.f;

#pragma unroll
    for (int p = 0; p < 2; p++) {
        const float* ap = aptr + (size_t)p * 32;
        const float* bp = bptr + (size_t)p * 32;
        const int so = p * 128 * 36;
#pragma unroll
        for (int u = 0; u < 4; u++) {
            int r = crow + u * 32;
            CP_ASYNC16(as_u32 + (uint32_t)(so + r * 36 + ccol) * 4,
                       ap + (size_t)u * 32 * K);
            CP_ASYNC16(bs_u32 + (uint32_t)(so + r * 36 + ccol) * 4,
                       bp + (size_t)u * 32 * K);
        }
        CP_COMMIT();
    }

    const int kTiles = K >> 5;
    int cur = 0, nslot = 2;
    for (int kt = 0; kt < kTiles; kt++) {
        CP_WAIT(1);
        __syncthreads();
        if (kt + 2 < kTiles) {
            const float* ap = aptr + (size_t)(kt + 2) * 32;
            const float* bp = bptr + (size_t)(kt + 2) * 32;
            const int so = nslot * 128 * 36;
#pragma unroll
            for (int u = 0; u < 4; u++) {
                int r = crow + u * 32;
                CP_ASYNC16(as_u32 + (uint32_t)(so + r * 36 + ccol) * 4,
                           ap + (size_t)u * 32 * K);
                CP_ASYNC16(bs_u32 + (uint32_t)(so + r * 36 + ccol) * 4,
                           bp + (size_t)u * 32 * K);
            }
        }
        CP_COMMIT();

        const int co = cur * 128 * 36;
#pragma unroll
        for (int ks = 0; ks < 4; ks++) {
            const int k0 = ks * 8;
            uint32_t af[4][4];
#pragma unroll
            for (int mf = 0; mf < 4; mf++) {
                int row = warp_m + mf * 16;
                af[mf][0] = __float_as_uint(As[co + (row + g    ) * 36 + k0 + tig    ]);
                af[mf][1] = __float_as_uint(As[co + (row + g + 8) * 36 + k0 + tig    ]);
                af[mf][2] = __float_as_uint(As[co + (row + g    ) * 36 + k0 + tig + 4]);
                af[mf][3] = __float_as_uint(As[co + (row + g + 8) * 36 + k0 + tig + 4]);
            }
            uint32_t bf[4][2];
#pragma unroll
            for (int nf = 0; nf < 4; nf++) {
                int col = warp_n + nf * 8;
                bf[nf][0] = __float_as_uint(Bs[co + (col + g) * 36 + k0 + tig    ]);
                bf[nf][1] = __float_as_uint(Bs[co + (col + g) * 36 + k0 + tig + 4]);
            }
#pragma unroll
            for (int mf = 0; mf < 4; mf++)
#pragma unroll
                for (int nf = 0; nf < 4; nf++)
                    mma_tf32_16x8x8(acc[mf][nf][0], acc[mf][nf][1],
                                    acc[mf][nf][2], acc[mf][nf][3],
                                    af[mf][0], af[mf][1], af[mf][2], af[mf][3],
                                    bf[nf][0], bf[nf][1]);
        }
        cur   = (cur + 1 == GSTAGES) ? 0 : cur + 1;
        nslot = (nslot + 1 == GSTAGES) ? 0 : nslot + 1;
    }

#pragma unroll
    for (int mf = 0; mf < 4; mf++) {
        int row0 = bm + warp_m + mf * 16 + g;
#pragma unroll
        for (int nf = 0; nf < 4; nf++) {
            int col = bn + warp_n + nf * 8 + 2 * tig;
            float bv0 = bias[col], bv1 = bias[col + 1];
            float v00 = (acc[mf][nf][0] + bv0) * oscale;
            float v01 = (acc[mf][nf][1] + bv1) * oscale;
            float v10 = (acc[mf][nf][2] + bv0) * oscale;
            float v11 = (acc[mf][nf][3] + bv1) * oscale;
            if (oround) {
                v00 = to_tf32(v00); v01 = to_tf32(v01);
                v10 = to_tf32(v10); v11 = to_tf32(v11);
            }
            *(float2*)&C[(size_t)row0 * N + col]       = make_float2(v00, v01);
            *(float2*)&C[(size_t)(row0 + 8) * N + col] = make_float2(v10, v11);
        }
    }
}

// ---------------------------------------------------------------------------
__global__ __launch_bounds__(256, 2) void gemm_qkv_fused(
    const float* __restrict__ qin, const float* __restrict__ kvin,
    const float* __restrict__ wq, const float* __restrict__ bq, float* __restrict__ qb,
    const float* __restrict__ wk, const float* __restrict__ bk, float* __restrict__ kb,
    const float* __restrict__ wv, const float* __restrict__ bv, float* __restrict__ vb)
{
    extern __shared__ float gsm[];
    const int y = blockIdx.y;
    const int bn = blockIdx.x * 128;
    if (y < 64) {
        gemm_body(gsm, qin, wq, bq, qb, y * 128, bn, SCALE, 1);
    } else if (y < 160) {
        gemm_body(gsm, kvin, wk, bk, kb, (y - 64) * 128, bn, 1.0f, 1);
    } else {
        gemm_body(gsm, kvin, wv, bv, vb, (y - 160) * 128, bn, 1.0f, 1);
    }
}

__global__ __launch_bounds__(256, 2) void gemm_o_proj(
    const float* __restrict__ cb, const float* __restrict__ wo,
    const float* __restrict__ bo, float* __restrict__ out)
{
    extern __shared__ float gsm[];
    gemm_body(gsm, cb, wo, bo, out, blockIdx.y * 128, blockIdx.x * 128, 1.0f, 0);
}

// ---------------------------------------------------------------------------
__device__ __forceinline__ void stage_kv(
    uint32_t ks_u32, uint32_t vs_u32, uint32_t ms_u32, int slot,
    const float* kp, const float* vp, const unsigned char* mp,
    int sr, int sc, int tid)
{
#pragma unroll
    for (int u = 0; u < 4; u++) {
        int r = sr + u * 16;
        CP_ASYNC16(ks_u32 + (uint32_t)(slot * BKV * LDS_K + r * LDS_K + sc) * 4,
                   kp + (size_t)r * D_MODEL + sc);
        CP_ASYNC16(vs_u32 + (uint32_t)(slot * BKV * LDS_V + r * LDS_V + sc) * 4,
                   vp + (size_t)r * D_MODEL + sc);
    }
    if (tid < 4)
        CP_ASYNC16(ms_u32 + (uint32_t)(slot * BKV + tid * 16), mp + tid * 16);
}

// ---------------------------------------------------------------------------
// Tensor-core flash attention (R13): cp.async 2-stage ring, 2 CTAs/SM,
// tf32-rounded epilogue.
// ---------------------------------------------------------------------------
__global__ __launch_bounds__(256, 2) void attn_tc_kernel(
    const float* __restrict__ qb, const float* __restrict__ kb,
    const float* __restrict__ vb, const unsigned char* __restrict__ mask,
    float* __restrict__ ctx)
{
    extern __shared__ float sm[];
    float* Ps = sm;                               // [128][LDS_P]
    float* Ks = Ps + BQ * LDS_P;                  // [2][64][LDS_K]
    float* Vs = Ks + STAGES * BKV * LDS_K;        // [2][64][LDS_V]
    unsigned char* Ms = (unsigned char*)(Vs + STAGES * BKV * LDS_V);  // [2][64]

    const int tid  = threadIdx.x;
    const int wid  = tid >> 5;
    const int lane = tid & 31;
    const int g    = lane >> 2;
    const int tig  = lane & 3;
    const int qr0  = wid * 16;
    const int b = blockIdx.y / NH;
    const int h = blockIdx.y % NH;
    const int t0 = blockIdx.x * BQ;

    const int sr = tid >> 4;
    const int sc = (tid & 15) * 4;

    const uint32_t ps_u32 = smem_u32(Ps);
    const uint32_t ks_u32 = smem_u32(Ks);
    const uint32_t vs_u32 = smem_u32(Vs);
    const uint32_t ms_u32 = smem_u32(Ms);

    const float* qbase = qb + ((size_t)b * TQ + t0) * D_MODEL + h * HDIM;
    const float* kbase = kb + ((size_t)b * NKV) * D_MODEL + h * HDIM;
    const float* vbase = vb + ((size_t)b * NKV) * D_MODEL + h * HDIM;
    const unsigned char* mbase = mask + (size_t)b * NKV;

#pragma unroll
    for (int u = 0; u < 8; u++) {
        int idx = tid + u * 256;
        int r = idx >> 4, c = (idx & 15) * 4;
        CP_ASYNC16(ps_u32 + (uint32_t)(r * LDS_P + c) * 4,
                   qbase + (size_t)r * D_MODEL + c);
    }
    CP_COMMIT();
    stage_kv(ks_u32, vs_u32, ms_u32, 0, kbase, vbase, mbase, sr, sc, tid);
    CP_COMMIT();

    CP_WAIT(1);
    __syncthreads();

    uint32_t qa[8][4];
#pragma unroll
    for (int ks = 0; ks < 8; ks++) {
        int k0 = ks * 8;
        qa[ks][0] = __float_as_uint(Ps[(qr0 + g    ) * LDS_P + k0 + tig    ]);
        qa[ks][1] = __float_as_uint(Ps[(qr0 + g + 8) * LDS_P + k0 + tig    ]);
        qa[ks][2] = __float_as_uint(Ps[(qr0 + g    ) * LDS_P + k0 + tig + 4]);
        qa[ks][3] = __float_as_uint(Ps[(qr0 + g + 8) * LDS_P + k0 + tig + 4]);
    }

    float m0 = -1e30f, m1 = -1e30f, l0 = 0.f, l1 = 0.f;
    float o[8][4];
#pragma unroll
    for (int df = 0; df < 8; df++)
#pragma unroll
        for (int r = 0; r < 4; r++) o[df][r] = 0.f;

    const int nTiles = NKV / BKV;      // 24
    for (int t = 0; t < nTiles; t++) {
        const int slot = t & 1;
        CP_WAIT(0);
        __syncthreads();

        if (t + 1 < nTiles) {
            stage_kv(ks_u32, vs_u32, ms_u32, 1 - slot,
                     kbase + (size_t)(t + 1) * BKV * D_MODEL,
                     vbase + (size_t)(t + 1) * BKV * D_MODEL,
                     mbase + (t + 1) * BKV, sr, sc, tid);
        }
        CP_COMMIT();

        const int cK = slot * BKV * LDS_K;
        const int cV = slot * BKV * LDS_V;
        const int cM = slot * BKV;

        float s[8][4];
#pragma unroll
        for (int nf = 0; nf < 8; nf++) {
            s[nf][0] = 0.f; s[nf][1] = 0.f; s[nf][2] = 0.f; s[nf][3] = 0.f;
#pragma unroll
            for (int ks = 0; ks < 8; ks++) {
                int k0 = ks * 8;
                uint32_t b0 = __float_as_uint(Ks[cK + (nf * 8 + g) * LDS_K + k0 + tig    ]);
                uint32_t b1 = __float_as_uint(Ks[cK + (nf * 8 + g) * LDS_K + k0 + tig + 4]);
                mma_tf32_16x8x8(s[nf][0], s[nf][1], s[nf][2], s[nf][3],
                                qa[ks][0], qa[ks][1], qa[ks][2], qa[ks][3], b0, b1);
            }
        }

#pragma unroll
        for (int nf = 0; nf < 8; nf++) {
            int c0 = cM + nf * 8 + 2 * tig;
            if (Ms[c0])     { s[nf][0] = -1e30f; s[nf][2] = -1e30f; }
            if (Ms[c0 + 1]) { s[nf][1] = -1e30f; s[nf][3] = -1e30f; }
        }

        float rmax0 = -1e30f, rmax1 = -1e30f;
#pragma unroll
        for (int nf = 0; nf < 8; nf++) {
            rmax0 = fmaxf(rmax0, fmaxf(s[nf][0], s[nf][1]));
            rmax1 = fmaxf(rmax1, fmaxf(s[nf][2], s[nf][3]));
        }
        rmax0 = fmaxf(rmax0, __shfl_xor_sync(0xffffffffu, rmax0, 1));
        rmax0 = fmaxf(rmax0, __shfl_xor_sync(0xffffffffu, rmax0, 2));
        rmax1 = fmaxf(rmax1, __shfl_xor_sync(0xffffffffu, rmax1, 1));
        rmax1 = fmaxf(rmax1, __shfl_xor_sync(0xffffffffu, rmax1, 2));

        float mn0 = fmaxf(m0, rmax0), mn1 = fmaxf(m1, rmax1);
        float corr0 = __expf(m0 - mn0), corr1 = __expf(m1 - mn1);
        m0 = mn0; m1 = mn1;

        float rs0 = 0.f, rs1 = 0.f;
#pragma unroll
        for (int nf = 0; nf < 8; nf++) {
            s[nf][0] = __expf(s[nf][0] - mn0); rs0 += s[nf][0];
            s[nf][1] = __expf(s[nf][1] - mn0); rs0 += s[nf][1];
            s[nf][2] = __expf(s[nf][2] - mn1); rs1 += s[nf][2];
            s[nf][3] = __expf(s[nf][3] - mn1); rs1 += s[nf][3];
        }
        rs0 += __shfl_xor_sync(0xffffffffu, rs0, 1);
        rs0 += __shfl_xor_sync(0xffffffffu, rs0, 2);
        rs1 += __shfl_xor_sync(0xffffffffu, rs1, 1);
        rs1 += __shfl_xor_sync(0xffffffffu, rs1, 2);
        l0 = l0 * corr0 + rs0;
        l1 = l1 * corr1 + rs1;

#pragma unroll
        for (int nf = 0; nf < 8; nf++) {
            int col = nf * 8 + 2 * tig;
            *(float2*)&Ps[(qr0 + g    ) * LDS_P + col] =
                make_float2(to_tf32(s[nf][0]), to_tf32(s[nf][1]));
            *(float2*)&Ps[(qr0 + g + 8) * LDS_P + col] =
                make_float2(to_tf32(s[nf][2]), to_tf32(s[nf][3]));
        }
        __syncwarp();

#pragma unroll
        for (int df = 0; df < 8; df++) {
            o[df][0] *= corr0; o[df][1] *= corr0;
            o[df][2] *= corr1; o[df][3] *= corr1;
        }
#pragma unroll
        for (int ks = 0; ks < 8; ks++) {
            int k0 = ks * 8;
            uint32_t pa0 = __float_as_uint(Ps[(qr0 + g    ) * LDS_P + k0 + tig    ]);
            uint32_t pa1 = __float_as_uint(Ps[(qr0 + g + 8) * LDS_P + k0 + tig    ]);
            uint32_t pa2 = __float_as_uint(Ps[(qr0 + g    ) * LDS_P + k0 + tig + 4]);
            uint32_t pa3 = __float_as_uint(Ps[(qr0 + g + 8) * LDS_P + k0 + tig + 4]);
#pragma unroll
            for (int df = 0; df < 8; df++) {
                uint32_t vb0 = __float_as_uint(Vs[cV + (k0 + tig    ) * LDS_V + df * 8 + g]);
                uint32_t vb1 = __float_as_uint(Vs[cV + (k0 + tig + 4) * LDS_V + df * 8 + g]);
                mma_tf32_16x8x8(o[df][0], o[df][1], o[df][2], o[df][3],
                                pa0, pa1, pa2, pa3, vb0, vb1);
            }
        }
    }

    float inv0 = 1.f / l0, inv1 = 1.f / l1;
    float* obase = ctx + ((size_t)b * TQ + t0) * D_MODEL + h * HDIM;
#pragma unroll
    for (int df = 0; df < 8; df++) {
        int col = df * 8 + 2 * tig;
        *(float2*)&obase[(size_t)(qr0 + g    ) * D_MODEL + col] =
            make_float2(to_tf32(o[df][0] * inv0), to_tf32(o[df][1] * inv0));
        *(float2*)&obase[(size_t)(qr0 + g + 8) * D_MODEL + col] =
            make_float2(to_tf32(o[df][2] * inv1), to_tf32(o[df][3] * inv1));
    }
}

// ---------------------------------------------------------------------------
extern "C" void kernel_launch(void* const* d_in, const int* in_sizes, int n_in,
                              void* d_out, int out_size)
{
    const float* query = (const float*)d_in[0];
    const float* kv    = (const float*)d_in[1];
    const unsigned char* mask = (const unsigned char*)d_in[2];
    const float* Wq = (const float*)d_in[3];
    const float* bq = (const float*)d_in[4];
    const float* Wk = (const float*)d_in[5];
    const float* bk = (const float*)d_in[6];
    const float* Wv = (const float*)d_in[7];
    const float* bv = (const float*)d_in[8];
    const float* Wo = (const float*)d_in[9];
    const float* bo = (const float*)d_in[10];
    float* out = (float*)d_out;

    static float *qb = nullptr, *kb = nullptr, *vbuf = nullptr, *cb = nullptr;
    static float *qin = nullptr, *kvin = nullptr;
    static float *wq = nullptr, *wk = nullptr, *wv = nullptr, *wo = nullptr;
    static const int SMEM_GEMM = GSTAGES * 2 * 128 * 36 * 4;              // 110592
    static const int SMEM_ATTN =
        (BQ * LDS_P + STAGES * BKV * LDS_K + STAGES * BKV * LDS_V) * 4
        + STAGES * BKV;                                                    // 106624
    if (!qb) {
        cudaGetSymbolAddress((void**)&qb,   g_q);
        cudaGetSymbolAddress((void**)&kb,   g_k);
        cudaGetSymbolAddress((void**)&vbuf, g_v);
        cudaGetSymbolAddress((void**)&cb,   g_ctx);
        cudaGetSymbolAddress((void**)&qin,  g_qin);
        cudaGetSymbolAddress((void**)&kvin, g_kvin);
        cudaGetSymbolAddress((void**)&wq,   g_wq);
        cudaGetSymbolAddress((void**)&wk,   g_wk);
        cudaGetSymbolAddress((void**)&wv,   g_wv);
        cudaGetSymbolAddress((void**)&wo,   g_wo);
        cudaFuncSetAttribute(gemm_qkv_fused,
                             cudaFuncAttributeMaxDynamicSharedMemorySize, SMEM_GEMM);
        cudaFuncSetAttribute(gemm_o_proj,
                             cudaFuncAttributeMaxDynamicSharedMemorySize, SMEM_GEMM);
        cudaFuncSetAttribute(attn_tc_kernel,
                             cudaFuncAttributeMaxDynamicSharedMemorySize, SMEM_ATTN);
    }

    dim3 blk(256);
    // tf32 rounding of all GEMM inputs: 25165824 floats / 16 / 256 = 6144 blocks
    cvt_all_kernel<<<6144, blk>>>(query, qin, kv, kvin,
                                  Wq, wq, Wk, wk, Wv, wv, Wo, wo);

    gemm_qkv_fused<<<dim3(8, 256), blk, SMEM_GEMM>>>(
        qin, kvin, wq, bq, qb, wk, bk, kb, wv, bv, vbuf);

    attn_tc_kernel<<<dim3(TQ / BQ, B_ * NH), blk, SMEM_ATTN>>>(qb, kb, vbuf, mask, cb);

    gemm_o_proj<<<dim3(8, 64), blk, SMEM_GEMM>>>(cb, wo, bo, out);
}